// round 15
// baseline (speedup 1.0000x reference)
#include <cuda_runtime.h>
#include <cuda_bf16.h>
#include <math.h>

#define BATCH   4096
#define D1      200
#define NREL    500
#define NRELP   512
#define M1      288
#define OC      32
#define FW      9
#define WOUT    392
#define WIN     400
#define VPAD    512
#define FCLEN   12544
#define EPSBN   1e-5f
#define NSPLIT  16
#define ILEN    25
#define FBLK    49
#define K1B     784      // NSPLIT*FBLK

#define DPADB   208
#define W2ROWS  224
#define W2PAD   512
#define KSPL_A  24
#define KLEN_A  12       // 288/24
#define KSPL_B  16
#define KLEN_B  13       // 208/16

typedef unsigned long long ull;

__device__ __forceinline__ void ffma2(ull &d, ull a, ull b) {
    asm("fma.rn.f32x2 %0, %1, %2, %0;" : "+l"(d) : "l"(a), "l"(b));
}
__device__ __forceinline__ ull dup2(float x) {
    ull r; asm("mov.b64 %0, {%1, %1};" : "=l"(r) : "f"(x)); return r;
}
__device__ __forceinline__ void unpack2(float &lo, float &hi, ull v) {
    asm("mov.b64 {%0, %1}, %2;" : "=f"(lo), "=f"(hi) : "l"(v));
}

// ---------------- device scratch (zero-initialized BSS) ----------------
__device__ float g_vp[NSPLIT * FCLEN];
__device__ float g_RT[DPADB * NRELP];           // rows 201+ stay zero
__device__ float g_Vmat[M1 * VPAD];             // pad cols stay zero
__device__ float g_w2p[KSPL_A * W2ROWS * W2PAD];// rows 201+ of each plane stay 0
__device__ float g_W2[W2ROWS * W2PAD];
__device__ float g_qp[KSPL_B * NREL * WIN];
__device__ float g_q[NREL * WIN];
__device__ float g_c1[OC];
__device__ float g_scal0;

// ======== K1': v partials + scal0 + R^T + ones row ======================
__global__ void __launch_bounds__(256) k1_v(
        const float* __restrict__ fcw,
        const float* __restrict__ bn2g, const float* __restrict__ bn2b,
        const float* __restrict__ bn2m, const float* __restrict__ bn2v,
        const float* __restrict__ fc2w, const float* __restrict__ fc2b,
        const float* __restrict__ fcb,  const float* __restrict__ R) {
    int tid = threadIdx.x;
    int bid = blockIdx.x;
    if (bid < K1B) {                         // ---- v partials ----
        __shared__ float sa[ILEN];
        int isp = bid / FBLK, fb = bid % FBLK;
        if (tid < ILEN) {
            int i = isp * ILEN + tid;
            float s2 = bn2g[i] * rsqrtf(bn2v[i] + EPSBN);
            sa[tid] = s2 * fc2w[i];
        }
        __syncthreads();
        int f = fb * 256 + tid;
        const float* __restrict__ p = fcw + (size_t)isp * ILEN * FCLEN + f;
        float acc = 0.f;
#pragma unroll
        for (int ii = 0; ii < ILEN; ii++)
            acc = fmaf(sa[ii], p[(size_t)ii * FCLEN], acc);
        g_vp[isp * FCLEN + f] = acc;
        return;
    }
    if (bid == K1B) {                        // ---- scal0 ----
        __shared__ float red[256];
        float t = 0.f;
        for (int i = tid; i < WIN; i += 256) {
            float s2 = bn2g[i] * rsqrtf(bn2v[i] + EPSBN);
            float a  = s2 * fc2w[i];
            t += (bn2b[i] - bn2m[i] * s2) * fc2w[i] + a * fcb[i];
        }
        red[tid] = t;
        __syncthreads();
        for (int s = 128; s; s >>= 1) { if (tid < s) red[tid] += red[tid + s]; __syncthreads(); }
        if (tid == 0) g_scal0 = red[0] + fc2b[0];
        return;
    }
    if (bid == K1B + 1 + 112) {              // ---- ones row (d=200) ----
        for (int i = tid; i < NRELP; i += 256) g_RT[200 * NRELP + i] = 1.0f;
        return;
    }
    // ---- R^T tile ----
    __shared__ float tile[32][33];
    int tb = bid - (K1B + 1);
    int dt = tb / 16, rt = tb % 16;
    int d0 = dt * 32, r0 = rt * 32;
    int tx = tid & 31, ty = tid >> 5;
    for (int rr = ty; rr < 32; rr += 8) {
        int rel = r0 + rr, d = d0 + tx;
        tile[rr][tx] = (rel < NREL && d < 200) ? R[rel * 200 + d] : 0.f;
    }
    __syncthreads();
    for (int rr = ty; rr < 32; rr += 8) {
        int d = d0 + rr, rel = r0 + tx;
        if (d < 200) g_RT[d * NRELP + rel] = tile[tx][rr];
    }
}

// ======== KV2: Vmat rows, 288 blocks (o,j) ==============================
__global__ void __launch_bounds__(256) kv_build(
        const float* __restrict__ bn1g, const float* __restrict__ bn1b,
        const float* __restrict__ bn1m, const float* __restrict__ bn1v) {
    __shared__ float red[256];
    int bid = blockIdx.x;
    int o = bid / FW, j = bid % FW;
    int tid = threadIdx.x;
    float inv1 = bn1g[o] * rsqrtf(bn1v[o] + EPSBN);
    float vsum = 0.f;
    for (int t = tid; t < WIN; t += 256) {
        int w = t - j;
        float val = 0.f;
        if ((unsigned)w < (unsigned)WOUT) {
            float s = 0.f;
#pragma unroll
            for (int sp = 0; sp < NSPLIT; sp++) s += g_vp[sp * FCLEN + o * WOUT + w];
            val = s * inv1;
            vsum += s;
        }
        g_Vmat[bid * VPAD + t] = val;
    }
    if (j == 0) {
        red[tid] = vsum;
        __syncthreads();
        for (int s = 128; s; s >>= 1) { if (tid < s) red[tid] += red[tid + s]; __syncthreads(); }
        if (tid == 0) g_c1[o] = (bn1b[o] - bn1m[o] * inv1) * red[0];
    }
}

// ======== GEMM-A: W2 partials = fc1w_ext^T @ Vmat (K-split 24) ==========
__global__ void __launch_bounds__(128) gemmA(
        const float* __restrict__ fc1w, const float* __restrict__ fc1b) {
    __shared__ float sA[KLEN_A][36];
    __shared__ float sB[KLEN_A][68];
    int tid = threadIdx.x;
    int d0 = blockIdx.x * 32;
    int t0 = blockIdx.y * 64;
    int m0 = blockIdx.z * KLEN_A;

    for (int i = tid; i < KLEN_A * 32; i += 128) {
        int kk = i >> 5, dd = i & 31;
        int d = d0 + dd, m = m0 + kk;
        float v = 0.f;
        if (d < 200) v = fc1w[m * 200 + d];
        else if (d == 200) v = fc1b[m];
        sA[kk][dd] = v;
    }
    for (int i = tid; i < KLEN_A * 16; i += 128) {
        int kk = i >> 4, c = i & 15;
        *(float4*)&sB[kk][c * 4] =
            *(const float4*)&g_Vmat[(size_t)(m0 + kk) * VPAD + t0 + c * 4];
    }
    __syncthreads();

    int tx = tid & 15, ty = tid >> 4;
    ull acc[2][4] = {};
#pragma unroll
    for (int kk = 0; kk < KLEN_A; kk++) {
        ull a01 = *(const ull*)&sA[kk][ty * 4];
        ull a23 = *(const ull*)&sA[kk][ty * 4 + 2];
        float4 b4 = *(const float4*)&sB[kk][tx * 4];
        ull bx = dup2(b4.x), by = dup2(b4.y), bz = dup2(b4.z), bw = dup2(b4.w);
        ffma2(acc[0][0], a01, bx); ffma2(acc[0][1], a01, by);
        ffma2(acc[0][2], a01, bz); ffma2(acc[0][3], a01, bw);
        ffma2(acc[1][0], a23, bx); ffma2(acc[1][1], a23, by);
        ffma2(acc[1][2], a23, bz); ffma2(acc[1][3], a23, bw);
    }
    float r[4][4];
#pragma unroll
    for (int n = 0; n < 4; n++) {
        unpack2(r[0][n], r[1][n], acc[0][n]);
        unpack2(r[2][n], r[3][n], acc[1][n]);
    }
    float* __restrict__ wp = g_w2p + (size_t)blockIdx.z * (W2ROWS * W2PAD);
    int gn = t0 + tx * 4;
#pragma unroll
    for (int mi = 0; mi < 4; mi++) {
        int d = d0 + ty * 4 + mi;
        if (d < 201) {
            float4 v = make_float4(r[mi][0], r[mi][1], r[mi][2], r[mi][3]);
            *(float4*)&wp[d * W2PAD + gn] = v;
        }
    }
}

// ======== FOLD-W2: 24 planes ============================================
__global__ void __launch_bounds__(128) fold_w2() {
    int idx = blockIdx.x * 128 + threadIdx.x;     // 28672 f4 / 128 = 224 blocks
    float4 s = make_float4(0.f, 0.f, 0.f, 0.f);
#pragma unroll
    for (int p = 0; p < KSPL_A; p++) {
        float4 t = ((const float4*)(g_w2p + (size_t)p * (W2ROWS * W2PAD)))[idx];
        s.x += t.x; s.y += t.y; s.z += t.z; s.w += t.w;
    }
    ((float4*)g_W2)[idx] = s;
}

// ======== GEMM-B: q partials = RT^T @ W2 (K-split 16) ===================
__global__ void __launch_bounds__(128) gemmB() {
    __shared__ float sR[KLEN_B][36];
    __shared__ float sW[KLEN_B][68];
    int tid = threadIdx.x;
    int r0 = blockIdx.x * 32;
    int t0 = blockIdx.y * 64;
    int k0 = blockIdx.z * KLEN_B;

    for (int i = tid; i < KLEN_B * 8; i += 128) {
        int kk = i >> 3, c = i & 7;
        *(float4*)&sR[kk][c * 4] =
            *(const float4*)&g_RT[(size_t)(k0 + kk) * NRELP + r0 + c * 4];
    }
    for (int i = tid; i < KLEN_B * 16; i += 128) {
        int kk = i >> 4, c = i & 15;
        *(float4*)&sW[kk][c * 4] =
            *(const float4*)&g_W2[(size_t)(k0 + kk) * W2PAD + t0 + c * 4];
    }
    __syncthreads();

    int tx = tid & 15, ty = tid >> 4;
    ull acc[2][4] = {};
#pragma unroll
    for (int kk = 0; kk < KLEN_B; kk++) {
        ull a01 = *(const ull*)&sR[kk][ty * 4];
        ull a23 = *(const ull*)&sR[kk][ty * 4 + 2];
        float4 b4 = *(const float4*)&sW[kk][tx * 4];
        ull bx = dup2(b4.x), by = dup2(b4.y), bz = dup2(b4.z), bw = dup2(b4.w);
        ffma2(acc[0][0], a01, bx); ffma2(acc[0][1], a01, by);
        ffma2(acc[0][2], a01, bz); ffma2(acc[0][3], a01, bw);
        ffma2(acc[1][0], a23, bx); ffma2(acc[1][1], a23, by);
        ffma2(acc[1][2], a23, bz); ffma2(acc[1][3], a23, bw);
    }
    float r[4][4];
#pragma unroll
    for (int n = 0; n < 4; n++) {
        unpack2(r[0][n], r[1][n], acc[0][n]);
        unpack2(r[2][n], r[3][n], acc[1][n]);
    }
    float* __restrict__ qp = g_qp + (size_t)blockIdx.z * (NREL * WIN);
    int gn = t0 + tx * 4;
    if (gn < WIN) {
#pragma unroll
        for (int mi = 0; mi < 4; mi++) {
            int gm = r0 + ty * 4 + mi;
            if (gm < NREL) {
                float4 v = make_float4(r[mi][0], r[mi][1], r[mi][2], r[mi][3]);
                *(float4*)&qp[gm * WIN + gn] = v;
            }
        }
    }
}

// ======== FOLD-Q: 16 planes =============================================
__global__ void __launch_bounds__(128) fold_q() {
    int idx = blockIdx.x * 128 + threadIdx.x;     // 50000 f4
    if (idx >= NREL * WIN / 4) return;
    float4 s = make_float4(0.f, 0.f, 0.f, 0.f);
#pragma unroll
    for (int p = 0; p < KSPL_B; p++) {
        float4 t = ((const float4*)(g_qp + (size_t)p * (NREL * WIN)))[idx];
        s.x += t.x; s.y += t.y; s.z += t.z; s.w += t.w;
    }
    ((float4*)g_q)[idx] = s;
}

// ======== K4 v5: one warp per example, 256-thr blocks ===================
__global__ void __launch_bounds__(256) k4_main(
        const int* __restrict__ e1i, const int* __restrict__ ri,
        const int* __restrict__ e2i, const float* __restrict__ Et,
        const float* __restrict__ bn0g, const float* __restrict__ bn0b,
        const float* __restrict__ bn0m, const float* __restrict__ bn0v,
        const float* __restrict__ bias, float* __restrict__ out) {
    int warp = threadIdx.x >> 5, lane = threadIdx.x & 31;
    int b = blockIdx.x * 8 + warp;
    float s0 = bn0g[0] * rsqrtf(bn0v[0] + EPSBN);
    float c0 = bn0b[0] - bn0m[0] * s0;
    int r = ri[b], e1 = e1i[b], e2 = e2i[b];
    const float4* __restrict__ E1 = (const float4*)(Et + (size_t)e1 * D1);
    const float4* __restrict__ E2 = (const float4*)(Et + (size_t)e2 * D1);
    const float4* __restrict__ Q  = (const float4*)(g_q + r * WIN);
    bool hi = lane < 18;
    float4 a0 = E1[lane],      q0 = Q[lane];
    float4 c0v = E2[lane],     q2 = Q[50 + lane];
    float4 a1, q1, c1v, q3;
    if (hi) {
        a1  = E1[lane + 32];   q1 = Q[lane + 32];
        c1v = E2[lane + 32];   q3 = Q[82 + lane];
    }
    float acc = g_c1[lane];
    acc = fmaf(fmaf(s0, a0.x, c0), q0.x, acc);
    acc = fmaf(fmaf(s0, a0.y, c0), q0.y, acc);
    acc = fmaf(fmaf(s0, a0.z, c0), q0.z, acc);
    acc = fmaf(fmaf(s0, a0.w, c0), q0.w, acc);
    acc = fmaf(fmaf(s0, c0v.x, c0), q2.x, acc);
    acc = fmaf(fmaf(s0, c0v.y, c0), q2.y, acc);
    acc = fmaf(fmaf(s0, c0v.z, c0), q2.z, acc);
    acc = fmaf(fmaf(s0, c0v.w, c0), q2.w, acc);
    if (hi) {
        acc = fmaf(fmaf(s0, a1.x, c0), q1.x, acc);
        acc = fmaf(fmaf(s0, a1.y, c0), q1.y, acc);
        acc = fmaf(fmaf(s0, a1.z, c0), q1.z, acc);
        acc = fmaf(fmaf(s0, a1.w, c0), q1.w, acc);
        acc = fmaf(fmaf(s0, c1v.x, c0), q3.x, acc);
        acc = fmaf(fmaf(s0, c1v.y, c0), q3.y, acc);
        acc = fmaf(fmaf(s0, c1v.z, c0), q3.z, acc);
        acc = fmaf(fmaf(s0, c1v.w, c0), q3.w, acc);
    }
    for (int o = 16; o; o >>= 1) acc += __shfl_down_sync(0xffffffffu, acc, o);
    if (lane == 0) out[b] = tanhf(acc + g_scal0) + bias[0];
}

// ---------------- launch ------------------------------------------------
extern "C" void kernel_launch(void* const* d_in, const int* in_sizes, int n_in,
                              void* d_out, int out_size) {
    const int*   e1_idx  = (const int*)  d_in[0];
    const int*   r_idx   = (const int*)  d_in[1];
    const int*   e2_idx  = (const int*)  d_in[2];
    const float* E_table = (const float*)d_in[3];
    const float* R_table = (const float*)d_in[4];
    const float* bn0g    = (const float*)d_in[5];
    const float* bn0b    = (const float*)d_in[6];
    const float* bn0m    = (const float*)d_in[7];
    const float* bn0v    = (const float*)d_in[8];
    const float* fc1w    = (const float*)d_in[9];
    const float* fc1b    = (const float*)d_in[10];
    const float* bn1g    = (const float*)d_in[11];
    const float* bn1b    = (const float*)d_in[12];
    const float* bn1m    = (const float*)d_in[13];
    const float* bn1v    = (const float*)d_in[14];
    const float* fcw     = (const float*)d_in[15];
    const float* fcb     = (const float*)d_in[16];
    const float* bn2g    = (const float*)d_in[17];
    const float* bn2b    = (const float*)d_in[18];
    const float* bn2m    = (const float*)d_in[19];
    const float* bn2v    = (const float*)d_in[20];
    const float* fc2w    = (const float*)d_in[21];
    const float* fc2b    = (const float*)d_in[22];
    const float* bias    = (const float*)d_in[23];
    float* out = (float*)d_out;

    k1_v<<<K1B + 1 + 112 + 1, 256>>>(fcw, bn2g, bn2b, bn2m, bn2v,
                                     fc2w, fc2b, fcb, R_table);
    kv_build<<<M1, 256>>>(bn1g, bn1b, bn1m, bn1v);
    gemmA<<<dim3(7, 7, KSPL_A), 128>>>(fc1w, fc1b);
    fold_w2<<<(W2ROWS * W2PAD / 4) / 128, 128>>>();
    gemmB<<<dim3(16, 7, KSPL_B), 128>>>();
    fold_q<<<(NREL * WIN / 4 + 127) / 128, 128>>>();
    k4_main<<<BATCH / 8, 256>>>(e1_idx, r_idx, e2_idx, E_table,
                                bn0g, bn0b, bn0m, bn0v, bias, out);
}

// round 16
// speedup vs baseline: 1.0748x; 1.0748x over previous
#include <cuda_runtime.h>
#include <cuda_bf16.h>
#include <math.h>

#define BATCH   4096
#define D1      200
#define NREL    500
#define NRELP   512
#define M1      288
#define OC      32
#define FW      9
#define WOUT    392
#define WIN     400
#define VPAD    512
#define FCLEN   12544
#define FCL4    3136     // FCLEN/4
#define EPSBN   1e-5f
#define NSPLIT  16
#define ILEN    25
#define FBLK4   13       // ceil(3136/256)
#define K1B     208      // NSPLIT*FBLK4

#define DPADB   208
#define W2ROWS  224
#define W2PAD   512
#define KSPL_A  12
#define KLEN_A  24       // 288/12
#define KSPL_B  8
#define KLEN_B  26       // 208/8

typedef unsigned long long ull;

__device__ __forceinline__ void ffma2(ull &d, ull a, ull b) {
    asm("fma.rn.f32x2 %0, %1, %2, %0;" : "+l"(d) : "l"(a), "l"(b));
}
__device__ __forceinline__ ull dup2(float x) {
    ull r; asm("mov.b64 %0, {%1, %1};" : "=l"(r) : "f"(x)); return r;
}
__device__ __forceinline__ void unpack2(float &lo, float &hi, ull v) {
    asm("mov.b64 {%0, %1}, %2;" : "=f"(lo), "=f"(hi) : "l"(v));
}

// ---------------- device scratch (zero-initialized BSS) ----------------
__device__ float g_vp[NSPLIT * FCLEN];
__device__ float g_RT[DPADB * NRELP];           // rows 201+ stay zero
__device__ float g_Vmat[M1 * VPAD];             // pad cols stay zero
__device__ float g_w2p[KSPL_A * W2ROWS * W2PAD];
__device__ float g_W2[W2ROWS * W2PAD];
__device__ float g_qp[KSPL_B * NREL * WIN];
__device__ float g_q[NREL * WIN];
__device__ float g_c1[OC];
__device__ float g_scal0;

// ======== K1'': float4 v-partials + scal0 + R^T + ones row ==============
// blocks 0..207: v partials (LDG.128); 208: scal0; 209..320: R^T; 321: ones
__global__ void __launch_bounds__(256) k1_v(
        const float* __restrict__ fcw,
        const float* __restrict__ bn2g, const float* __restrict__ bn2b,
        const float* __restrict__ bn2m, const float* __restrict__ bn2v,
        const float* __restrict__ fc2w, const float* __restrict__ fc2b,
        const float* __restrict__ fcb,  const float* __restrict__ R) {
    int tid = threadIdx.x;
    int bid = blockIdx.x;
    if (bid < K1B) {                         // ---- v partials (f4) ----
        __shared__ float sa[ILEN];
        int isp = bid / FBLK4, fb = bid % FBLK4;
        if (tid < ILEN) {
            int i = isp * ILEN + tid;
            float s2 = bn2g[i] * rsqrtf(bn2v[i] + EPSBN);
            sa[tid] = s2 * fc2w[i];
        }
        __syncthreads();
        int f4 = fb * 256 + tid;
        if (f4 >= FCL4) return;
        const float4* __restrict__ p =
            (const float4*)fcw + (size_t)isp * ILEN * FCL4 + f4;
        float4 acc = make_float4(0.f, 0.f, 0.f, 0.f);
#pragma unroll
        for (int ii = 0; ii < ILEN; ii++) {
            float4 v = p[(size_t)ii * FCL4];
            float s = sa[ii];
            acc.x = fmaf(s, v.x, acc.x);
            acc.y = fmaf(s, v.y, acc.y);
            acc.z = fmaf(s, v.z, acc.z);
            acc.w = fmaf(s, v.w, acc.w);
        }
        ((float4*)g_vp)[(size_t)isp * FCL4 + f4] = acc;
        return;
    }
    if (bid == K1B) {                        // ---- scal0 ----
        __shared__ float red[256];
        float t = 0.f;
        for (int i = tid; i < WIN; i += 256) {
            float s2 = bn2g[i] * rsqrtf(bn2v[i] + EPSBN);
            float a  = s2 * fc2w[i];
            t += (bn2b[i] - bn2m[i] * s2) * fc2w[i] + a * fcb[i];
        }
        red[tid] = t;
        __syncthreads();
        for (int s = 128; s; s >>= 1) { if (tid < s) red[tid] += red[tid + s]; __syncthreads(); }
        if (tid == 0) g_scal0 = red[0] + fc2b[0];
        return;
    }
    if (bid == K1B + 1 + 112) {              // ---- ones row (d=200) ----
        for (int i = tid; i < NRELP; i += 256) g_RT[200 * NRELP + i] = 1.0f;
        return;
    }
    // ---- R^T tile ----
    __shared__ float tile[32][33];
    int tb = bid - (K1B + 1);
    int dt = tb / 16, rt = tb % 16;
    int d0 = dt * 32, r0 = rt * 32;
    int tx = tid & 31, ty = tid >> 5;
    for (int rr = ty; rr < 32; rr += 8) {
        int rel = r0 + rr, d = d0 + tx;
        tile[rr][tx] = (rel < NREL && d < 200) ? R[rel * 200 + d] : 0.f;
    }
    __syncthreads();
    for (int rr = ty; rr < 32; rr += 8) {
        int d = d0 + rr, rel = r0 + tx;
        if (d < 200) g_RT[d * NRELP + rel] = tile[tx][rr];
    }
}

// ======== KV2: Vmat rows, 288 blocks (o,j) ==============================
__global__ void __launch_bounds__(256) kv_build(
        const float* __restrict__ bn1g, const float* __restrict__ bn1b,
        const float* __restrict__ bn1m, const float* __restrict__ bn1v) {
    __shared__ float red[256];
    int bid = blockIdx.x;
    int o = bid / FW, j = bid % FW;
    int tid = threadIdx.x;
    float inv1 = bn1g[o] * rsqrtf(bn1v[o] + EPSBN);
    float vsum = 0.f;
    for (int t = tid; t < WIN; t += 256) {
        int w = t - j;
        float val = 0.f;
        if ((unsigned)w < (unsigned)WOUT) {
            float s = 0.f;
#pragma unroll
            for (int sp = 0; sp < NSPLIT; sp++) s += g_vp[sp * FCLEN + o * WOUT + w];
            val = s * inv1;
            vsum += s;
        }
        g_Vmat[bid * VPAD + t] = val;
    }
    if (j == 0) {
        red[tid] = vsum;
        __syncthreads();
        for (int s = 128; s; s >>= 1) { if (tid < s) red[tid] += red[tid + s]; __syncthreads(); }
        if (tid == 0) g_c1[o] = (bn1b[o] - bn1m[o] * inv1) * red[0];
    }
}

// ======== GEMM-A: W2 partials = fc1w_ext^T @ Vmat (K-split 12) ==========
__global__ void __launch_bounds__(128) gemmA(
        const float* __restrict__ fc1w, const float* __restrict__ fc1b) {
    __shared__ float sA[KLEN_A][36];
    __shared__ float sB[KLEN_A][68];
    int tid = threadIdx.x;
    int d0 = blockIdx.x * 32;
    int t0 = blockIdx.y * 64;
    int m0 = blockIdx.z * KLEN_A;

    for (int i = tid; i < KLEN_A * 32; i += 128) {
        int kk = i >> 5, dd = i & 31;
        int d = d0 + dd, m = m0 + kk;
        float v = 0.f;
        if (d < 200) v = fc1w[m * 200 + d];
        else if (d == 200) v = fc1b[m];
        sA[kk][dd] = v;
    }
    for (int i = tid; i < KLEN_A * 16; i += 128) {
        int kk = i >> 4, c = i & 15;
        *(float4*)&sB[kk][c * 4] =
            *(const float4*)&g_Vmat[(size_t)(m0 + kk) * VPAD + t0 + c * 4];
    }
    __syncthreads();

    int tx = tid & 15, ty = tid >> 4;
    ull acc[2][4] = {};
#pragma unroll
    for (int kk = 0; kk < KLEN_A; kk++) {
        ull a01 = *(const ull*)&sA[kk][ty * 4];
        ull a23 = *(const ull*)&sA[kk][ty * 4 + 2];
        float4 b4 = *(const float4*)&sB[kk][tx * 4];
        ull bx = dup2(b4.x), by = dup2(b4.y), bz = dup2(b4.z), bw = dup2(b4.w);
        ffma2(acc[0][0], a01, bx); ffma2(acc[0][1], a01, by);
        ffma2(acc[0][2], a01, bz); ffma2(acc[0][3], a01, bw);
        ffma2(acc[1][0], a23, bx); ffma2(acc[1][1], a23, by);
        ffma2(acc[1][2], a23, bz); ffma2(acc[1][3], a23, bw);
    }
    float r[4][4];
#pragma unroll
    for (int n = 0; n < 4; n++) {
        unpack2(r[0][n], r[1][n], acc[0][n]);
        unpack2(r[2][n], r[3][n], acc[1][n]);
    }
    float* __restrict__ wp = g_w2p + (size_t)blockIdx.z * (W2ROWS * W2PAD);
    int gn = t0 + tx * 4;
#pragma unroll
    for (int mi = 0; mi < 4; mi++) {
        int d = d0 + ty * 4 + mi;
        if (d < 201) {
            float4 v = make_float4(r[mi][0], r[mi][1], r[mi][2], r[mi][3]);
            *(float4*)&wp[d * W2PAD + gn] = v;
        }
    }
}

// ======== FOLD-W2: 12 planes ============================================
__global__ void __launch_bounds__(256) fold_w2() {
    int idx = blockIdx.x * 256 + threadIdx.x;
    float4 s = make_float4(0.f, 0.f, 0.f, 0.f);
#pragma unroll
    for (int p = 0; p < KSPL_A; p++) {
        float4 t = ((const float4*)(g_w2p + (size_t)p * (W2ROWS * W2PAD)))[idx];
        s.x += t.x; s.y += t.y; s.z += t.z; s.w += t.w;
    }
    ((float4*)g_W2)[idx] = s;
}

// ======== GEMM-B: q partials = RT^T @ W2 (K-split 8) ====================
__global__ void __launch_bounds__(128) gemmB() {
    __shared__ float sR[KLEN_B][36];
    __shared__ float sW[KLEN_B][68];
    int tid = threadIdx.x;
    int r0 = blockIdx.x * 32;
    int t0 = blockIdx.y * 64;
    int k0 = blockIdx.z * KLEN_B;

    for (int i = tid; i < KLEN_B * 8; i += 128) {
        int kk = i >> 3, c = i & 7;
        *(float4*)&sR[kk][c * 4] =
            *(const float4*)&g_RT[(size_t)(k0 + kk) * NRELP + r0 + c * 4];
    }
    for (int i = tid; i < KLEN_B * 16; i += 128) {
        int kk = i >> 4, c = i & 15;
        *(float4*)&sW[kk][c * 4] =
            *(const float4*)&g_W2[(size_t)(k0 + kk) * W2PAD + t0 + c * 4];
    }
    __syncthreads();

    int tx = tid & 15, ty = tid >> 4;
    ull acc[2][4] = {};
#pragma unroll
    for (int kk = 0; kk < KLEN_B; kk++) {
        ull a01 = *(const ull*)&sR[kk][ty * 4];
        ull a23 = *(const ull*)&sR[kk][ty * 4 + 2];
        float4 b4 = *(const float4*)&sW[kk][tx * 4];
        ull bx = dup2(b4.x), by = dup2(b4.y), bz = dup2(b4.z), bw = dup2(b4.w);
        ffma2(acc[0][0], a01, bx); ffma2(acc[0][1], a01, by);
        ffma2(acc[0][2], a01, bz); ffma2(acc[0][3], a01, bw);
        ffma2(acc[1][0], a23, bx); ffma2(acc[1][1], a23, by);
        ffma2(acc[1][2], a23, bz); ffma2(acc[1][3], a23, bw);
    }
    float r[4][4];
#pragma unroll
    for (int n = 0; n < 4; n++) {
        unpack2(r[0][n], r[1][n], acc[0][n]);
        unpack2(r[2][n], r[3][n], acc[1][n]);
    }
    float* __restrict__ qp = g_qp + (size_t)blockIdx.z * (NREL * WIN);
    int gn = t0 + tx * 4;
    if (gn < WIN) {
#pragma unroll
        for (int mi = 0; mi < 4; mi++) {
            int gm = r0 + ty * 4 + mi;
            if (gm < NREL) {
                float4 v = make_float4(r[mi][0], r[mi][1], r[mi][2], r[mi][3]);
                *(float4*)&qp[gm * WIN + gn] = v;
            }
        }
    }
}

// ======== FOLD-Q: 8 planes ==============================================
__global__ void __launch_bounds__(256) fold_q() {
    int idx = blockIdx.x * 256 + threadIdx.x;
    if (idx >= NREL * WIN / 4) return;
    float4 s = make_float4(0.f, 0.f, 0.f, 0.f);
#pragma unroll
    for (int p = 0; p < KSPL_B; p++) {
        float4 t = ((const float4*)(g_qp + (size_t)p * (NREL * WIN)))[idx];
        s.x += t.x; s.y += t.y; s.z += t.z; s.w += t.w;
    }
    ((float4*)g_q)[idx] = s;
}

// ======== K4 v4: one warp per example, no barrier, MLP-8 loads ==========
__global__ void __launch_bounds__(128) k4_main(
        const int* __restrict__ e1i, const int* __restrict__ ri,
        const int* __restrict__ e2i, const float* __restrict__ Et,
        const float* __restrict__ bn0g, const float* __restrict__ bn0b,
        const float* __restrict__ bn0m, const float* __restrict__ bn0v,
        const float* __restrict__ bias, float* __restrict__ out) {
    int warp = threadIdx.x >> 5, lane = threadIdx.x & 31;
    int b = blockIdx.x * 4 + warp;
    float s0 = bn0g[0] * rsqrtf(bn0v[0] + EPSBN);
    float c0 = bn0b[0] - bn0m[0] * s0;
    int r = ri[b], e1 = e1i[b], e2 = e2i[b];
    const float4* __restrict__ E1 = (const float4*)(Et + (size_t)e1 * D1);
    const float4* __restrict__ E2 = (const float4*)(Et + (size_t)e2 * D1);
    const float4* __restrict__ Q  = (const float4*)(g_q + r * WIN);
    bool hi = lane < 18;
    float4 a0 = E1[lane],      q0 = Q[lane];
    float4 c0v = E2[lane],     q2 = Q[50 + lane];
    float4 a1, q1, c1v, q3;
    if (hi) {
        a1  = E1[lane + 32];   q1 = Q[lane + 32];
        c1v = E2[lane + 32];   q3 = Q[82 + lane];
    }
    float acc = g_c1[lane];
    acc = fmaf(fmaf(s0, a0.x, c0), q0.x, acc);
    acc = fmaf(fmaf(s0, a0.y, c0), q0.y, acc);
    acc = fmaf(fmaf(s0, a0.z, c0), q0.z, acc);
    acc = fmaf(fmaf(s0, a0.w, c0), q0.w, acc);
    acc = fmaf(fmaf(s0, c0v.x, c0), q2.x, acc);
    acc = fmaf(fmaf(s0, c0v.y, c0), q2.y, acc);
    acc = fmaf(fmaf(s0, c0v.z, c0), q2.z, acc);
    acc = fmaf(fmaf(s0, c0v.w, c0), q2.w, acc);
    if (hi) {
        acc = fmaf(fmaf(s0, a1.x, c0), q1.x, acc);
        acc = fmaf(fmaf(s0, a1.y, c0), q1.y, acc);
        acc = fmaf(fmaf(s0, a1.z, c0), q1.z, acc);
        acc = fmaf(fmaf(s0, a1.w, c0), q1.w, acc);
        acc = fmaf(fmaf(s0, c1v.x, c0), q3.x, acc);
        acc = fmaf(fmaf(s0, c1v.y, c0), q3.y, acc);
        acc = fmaf(fmaf(s0, c1v.z, c0), q3.z, acc);
        acc = fmaf(fmaf(s0, c1v.w, c0), q3.w, acc);
    }
    for (int o = 16; o; o >>= 1) acc += __shfl_down_sync(0xffffffffu, acc, o);
    if (lane == 0) out[b] = tanhf(acc + g_scal0) + bias[0];
}

// ---------------- launch ------------------------------------------------
extern "C" void kernel_launch(void* const* d_in, const int* in_sizes, int n_in,
                              void* d_out, int out_size) {
    const int*   e1_idx  = (const int*)  d_in[0];
    const int*   r_idx   = (const int*)  d_in[1];
    const int*   e2_idx  = (const int*)  d_in[2];
    const float* E_table = (const float*)d_in[3];
    const float* R_table = (const float*)d_in[4];
    const float* bn0g    = (const float*)d_in[5];
    const float* bn0b    = (const float*)d_in[6];
    const float* bn0m    = (const float*)d_in[7];
    const float* bn0v    = (const float*)d_in[8];
    const float* fc1w    = (const float*)d_in[9];
    const float* fc1b    = (const float*)d_in[10];
    const float* bn1g    = (const float*)d_in[11];
    const float* bn1b    = (const float*)d_in[12];
    const float* bn1m    = (const float*)d_in[13];
    const float* bn1v    = (const float*)d_in[14];
    const float* fcw     = (const float*)d_in[15];
    const float* fcb     = (const float*)d_in[16];
    const float* bn2g    = (const float*)d_in[17];
    const float* bn2b    = (const float*)d_in[18];
    const float* bn2m    = (const float*)d_in[19];
    const float* bn2v    = (const float*)d_in[20];
    const float* fc2w    = (const float*)d_in[21];
    const float* fc2b    = (const float*)d_in[22];
    const float* bias    = (const float*)d_in[23];
    float* out = (float*)d_out;

    k1_v<<<K1B + 1 + 112 + 1, 256>>>(fcw, bn2g, bn2b, bn2m, bn2v,
                                     fc2w, fc2b, fcb, R_table);
    kv_build<<<M1, 256>>>(bn1g, bn1b, bn1m, bn1v);
    gemmA<<<dim3(7, 7, KSPL_A), 128>>>(fc1w, fc1b);
    fold_w2<<<(W2ROWS * W2PAD / 4) / 256, 256>>>();
    gemmB<<<dim3(16, 7, KSPL_B), 128>>>();
    fold_q<<<(NREL * WIN / 4 + 255) / 256, 256>>>();
    k4_main<<<BATCH / 4, 128>>>(e1_idx, r_idx, e2_idx, E_table,
                                bn0g, bn0b, bn0m, bn0v, bias, out);
}